// round 14
// baseline (speedup 1.0000x reference)
#include <cuda_runtime.h>
#include <math.h>

// ---------------- tuning ----------------
#define LCH  32               // samples per chunk
#define WARM 32               // warmup samples (measured ~1.4e-4 total rel_err)
#define TPB  32               // one warp per block
#define CHB  (2 * TPB)        // chunks per block = 64 (2 chains per thread)
#define NCH  8                // max hop rows per block region (2084 smp -> <=6)
#define LEAD 4                // region lead-in so per-thread j starts 4-aligned

struct Par {
    float b0, b1c, b2c, a1, a2, sF4, sFm;
    int Hm2;
};

struct Ch {                    // one filter chain's full state
    float x1, x2, f1, f2, f3, f4, y1, y2, y3, y4;
    float cb0, cb1, cb2, cb3, cb4, db0, db1, db2, db3, db4;
    float cd1, cd2, cd3, cd4, dd1, dd2, dd3, dd4;
    float fr, frLim;
    const float* rw;
    int i0, j;
};

__device__ __forceinline__ void ch_reload(Ch& c, int Hm2)
{
    const float* rw = c.rw;
    c.cb0 = rw[0];  c.cb1 = rw[1];  c.cb2 = rw[2];  c.cb3 = rw[3];  c.cb4 = rw[4];
    c.cd1 = rw[6];  c.cd2 = rw[7];  c.cd3 = rw[8];  c.cd4 = rw[9];
    c.db0 = rw[10] - c.cb0; c.db1 = rw[11] - c.cb1; c.db2 = rw[12] - c.cb2;
    c.db3 = rw[13] - c.cb3; c.db4 = rw[14] - c.cb4;
    c.dd1 = rw[16] - c.cd1; c.dd2 = rw[17] - c.cd2;
    c.dd3 = rw[18] - c.cd3; c.dd4 = rw[19] - c.cd4;
    c.frLim = (c.i0 < Hm2) ? 1.0f : 1e30f;
}

// group of 4 samples for one chain; DOST -> store into ys at q..q+3
template <bool DOST>
__device__ __forceinline__ void ch_group4(Ch& c, const float* __restrict__ xs,
                                          float* __restrict__ ys, int q,
                                          const Par& P, float g1v)
{
    if (c.fr >= c.frLim) {
        c.i0++; c.rw += 10;
        ch_reload(c, P.Hm2);
        c.fr -= 1.0f;
    }
    float frm = c.fr + P.sFm;
    float gc0 = fmaf(frm, c.db0, c.cb0);
    float gc1 = fmaf(frm, c.db1, c.cb1);
    float gc2 = fmaf(frm, c.db2, c.cb2);
    float gc3 = fmaf(frm, c.db3, c.cb3);
    float gc4 = fmaf(frm, c.db4, c.cb4);
    float gd1 = fmaf(frm, c.dd1, c.cd1);
    float gd2 = fmaf(frm, c.dd2, c.cd2);
    float gd3 = fmaf(frm, c.dd3, c.cd3);
    float gd4 = fmaf(frm, c.dd4, c.cd4);
    int jp = c.j + (c.j >> 5);

    float xa = xs[jp + 0];
    float v1 = fmaf(P.b2c, c.x2, fmaf(P.b1c, c.x1, P.b0 * xa));
    float ha = fmaf(-P.a2, c.f2, fmaf(-P.a1, c.f1, v1));
    float va = fmaf(gc0, ha, fmaf(gc1, c.f1, fmaf(gc2, c.f2, fmaf(gc3, c.f3, gc4 * c.f4))));
    float ya = fmaf(-gd1, c.y1, va - fmaf(gd2, c.y2, fmaf(gd3, c.y3, gd4 * c.y4)));
    if (DOST) { int qq = q + 0; ys[qq + (qq >> 5)] = fmaf(g1v, ha, ya); }

    float xb = xs[jp + 1];
    v1 = fmaf(P.b2c, c.x1, fmaf(P.b1c, xa, P.b0 * xb));
    float hb = fmaf(-P.a2, c.f1, fmaf(-P.a1, ha, v1));
    float vb = fmaf(gc0, hb, fmaf(gc1, ha, fmaf(gc2, c.f1, fmaf(gc3, c.f2, gc4 * c.f3))));
    float yb = fmaf(-gd1, ya, vb - fmaf(gd2, c.y1, fmaf(gd3, c.y2, gd4 * c.y3)));
    if (DOST) { int qq = q + 1; ys[qq + (qq >> 5)] = fmaf(g1v, hb, yb); }

    float xc = xs[jp + 2];
    v1 = fmaf(P.b2c, xa, fmaf(P.b1c, xb, P.b0 * xc));
    float hc = fmaf(-P.a2, ha, fmaf(-P.a1, hb, v1));
    float vc = fmaf(gc0, hc, fmaf(gc1, hb, fmaf(gc2, ha, fmaf(gc3, c.f1, gc4 * c.f2))));
    float yc = fmaf(-gd1, yb, vc - fmaf(gd2, ya, fmaf(gd3, c.y1, gd4 * c.y2)));
    if (DOST) { int qq = q + 2; ys[qq + (qq >> 5)] = fmaf(g1v, hc, yc); }

    float xd = xs[jp + 3];
    v1 = fmaf(P.b2c, xb, fmaf(P.b1c, xc, P.b0 * xd));
    float hd = fmaf(-P.a2, hb, fmaf(-P.a1, hc, v1));
    float vd = fmaf(gc0, hd, fmaf(gc1, hc, fmaf(gc2, hb, fmaf(gc3, ha, gc4 * c.f1))));
    float yd = fmaf(-gd1, yc, vd - fmaf(gd2, yb, fmaf(gd3, ya, gd4 * c.y1)));
    if (DOST) { int qq = q + 3; ys[qq + (qq >> 5)] = fmaf(g1v, hd, yd); }

    c.x2 = xc; c.x1 = xd;
    c.f4 = ha; c.f3 = hb; c.f2 = hc; c.f1 = hd;
    c.y4 = ya; c.y3 = yb; c.y2 = yc; c.y1 = yd;
    c.fr += P.sF4;
    c.j += 4;
}

// seed a chain at absolute sample n0 (xs index j0); zero filter state
__device__ __forceinline__ void ch_seed(Ch& c, int n0, int j0, float scaleF,
                                        int Hm2, const float* sc, int h0,
                                        const float* __restrict__ xs)
{
    c.j = j0;
    c.x1 = xs[(j0 - 1) + ((j0 - 1) >> 5)];
    c.x2 = xs[(j0 - 2) + ((j0 - 2) >> 5)];
    c.f1 = c.f2 = c.f3 = c.f4 = 0.f;
    c.y1 = c.y2 = c.y3 = c.y4 = 0.f;
    float pos0 = (float)n0 * scaleF;
    int i0 = (int)floorf(pos0);
    i0 = i0 < 0 ? 0 : (i0 > Hm2 ? Hm2 : i0);
    c.i0 = i0;
    c.rw = sc + (i0 - h0) * 10;
    ch_reload(c, Hm2);
    c.fr = pos0 - (float)i0;
}

__global__ void __launch_bounds__(TPB)
phaser_all(const float* __restrict__ x,
           const float* __restrict__ g1, const float* __restrict__ g2,
           const float* __restrict__ depth, const float* __restrict__ bias,
           const float* __restrict__ lfo_omega, const float* __restrict__ lfo_phi,
           const float* __restrict__ lfo_r_logit,
           const float* __restrict__ W_in, const float* __restrict__ b_in,
           const float* __restrict__ W_h, const float* __restrict__ b_h,
           const float* __restrict__ W_out, const float* __restrict__ b_out,
           const float* __restrict__ bq_dc, const float* __restrict__ bq_ff,
           const float* __restrict__ bq_fb,
           float* __restrict__ out, int N, int H, int out_size)
{
    constexpr int PAYN = CHB * LCH;                // 2048
    constexpr int REGN = PAYN + WARM + LEAD;       // 2084
    __shared__ float xs[REGN + (REGN >> 5) + 8];
    __shared__ float ys[PAYN + (PAYN >> 5) + 8];
    __shared__ float sc[NCH * 10];
    __shared__ float mh[2][NCH * 16];

    const int blockFirst      = blockIdx.x * CHB;  // first chunk id
    const int blockSampleBase = blockFirst * LCH;
    const int regionStart     = blockSampleBase - WARM - LEAD;
    const float scaleF = (float)((double)(H - 1) / (double)(N - 1));
    const int Hm2 = (H - 2) > 0 ? (H - 2) : 0;

    // ---- stage x into shared (coalesced; zeros outside [0,N)) ----
    for (int j = threadIdx.x; j < REGN; j += TPB) {
        int g = regionStart + j;
        xs[j + (j >> 5)] = (g >= 0 && g < N) ? x[g] : 0.f;
    }

    // ---- hop-row range this block needs ----
    int nmin = regionStart + LEAD; if (nmin < 0) nmin = 0;
    int nmaxx = blockSampleBase + PAYN; if (nmaxx > N) nmaxx = N;
    int i0min = (int)floorf((float)nmin * scaleF);
    if (i0min < 0) i0min = 0; if (i0min > Hm2) i0min = Hm2;
    int i0max = (int)floorf((float)(nmaxx - 1) * scaleF);
    if (i0max < 0) i0max = 0; if (i0max > Hm2) i0max = Hm2;
    const int h0 = i0min;
    int nh = i0max + 2 - h0; if (nh > NCH) nh = NCH;
    const int nwork = nh * 16;

    // ---- parallel MLP: layer 0 ----
    {
        float r    = 1.f / (1.f + expf(-lfo_r_logit[0]));
        float logr = logf(r);
        float om = lfo_omega[0], phi = lfo_phi[0];
        for (int w = threadIdx.x; w < nwork; w += TPB) {
            int hop = w >> 4, u = w & 15;
            float tf  = (float)(h0 + hop);
            float amp = expf(tf * logr);
            float ph  = om * tf + phi;
            float l0 = amp * cosf(ph), l1 = amp * sinf(ph);
            mh[0][w] = tanhf(l0 * W_in[u] + l1 * W_in[16 + u] + b_in[u]);
        }
    }
    __syncthreads();
#pragma unroll
    for (int lay = 0; lay < 2; lay++) {
        for (int w = threadIdx.x; w < nwork; w += TPB) {
            int hop = w >> 4, u = w & 15;
            const float* hv = &mh[lay & 1][hop << 4];
            float s = b_h[lay * 16 + u];
#pragma unroll
            for (int i = 0; i < 16; i++)
                s = fmaf(hv[i], W_h[lay * 256 + i * 16 + u], s);
            mh[(lay & 1) ^ 1][w] = tanhf(s);
        }
        __syncthreads();
    }
    // ---- output layer + allpass coefficient rows ----
    if (threadIdx.x < nh) {
        int t = h0 + threadIdx.x;
        const float* hv = &mh[0][threadIdx.x << 4];
        float s = b_out[0];
#pragma unroll
        for (int i = 0; i < 16; i++) s = fmaf(hv[i], W_out[i], s);
        float ws = tanhf(s);
        float dd = bias[0] + depth[0] * 0.5f * (1.f + ws);
        float td = tanf(dd);
        float p  = tanhf((1.f - td) / (1.f + td));
        float p2 = p * p, p3 = p2 * p, p4 = p2 * p2;
        float bap[5] = { p4, -4.f * p3, 6.f * p2, -4.f * p, 1.f };
        float aap[5] = { 1.f, -4.f * p, 6.f * p2, -4.f * p3, p4 };
        float ag2 = fabsf(g2[0]);
        float den0 = aap[0] - ag2 * bap[0];
        float* row = sc + threadIdx.x * 10;
#pragma unroll
        for (int k = 0; k < 5; k++) {
            float dk = aap[k] - ag2 * bap[k];
            row[k]     = bap[k] / den0;
            row[5 + k] = dk / den0;
        }
        if (N + t < out_size) out[N + t] = p;       // second output: p (H,)
        if (t == H - 1 && blockIdx.x == gridDim.x - 1)
            for (int q2 = N + H; q2 < out_size; q2++) out[q2] = p;
    }
    __syncthreads();

    // ---- per-thread dual chains ----
    {
        Par P;
        P.b0 = bq_dc[0]; P.b1c = bq_ff[0]; P.b2c = bq_ff[1];
        P.a1 = 2.f * tanhf(bq_fb[0]);
        float aa1 = fabsf(P.a1);
        P.a2 = ((2.f - aa1) * tanhf(bq_fb[1]) + aa1) * 0.5f;
        P.sF4 = 4.f * scaleF; P.sFm = 1.5f * scaleF; P.Hm2 = Hm2;
        const float g1v = g1[0];

        const int t = threadIdx.x;
        const int sA = blockSampleBase + t * LCH;            // chain A start
        const int sB = sA + TPB * LCH;                       // chain B start
        const bool fullA = (sA + LCH <= N);
        const bool fullB = (sB + LCH <= N);

        if (fullA && fullB) {
            // -------- dual fast path (uniform 8 warm + 8 payload groups) ----
            Ch A, B;
            // warmup reads zero-padded region; zero state preserved for sA<WARM
            ch_seed(A, sA - WARM, sA - WARM - regionStart, scaleF, Hm2, sc, h0, xs);
            ch_seed(B, sB - WARM, sB - WARM - regionStart, scaleF, Hm2, sc, h0, xs);
            constexpr int WG = WARM / 4, PG = LCH / 4;
#pragma unroll 2
            for (int g = 0; g < WG; g++) {
                ch_group4<false>(A, xs, ys, 0, P, g1v);
                ch_group4<false>(B, xs, ys, 0, P, g1v);
            }
            int qA = t * LCH, qB = (TPB + t) * LCH;
#pragma unroll 2
            for (int g = 0; g < PG; g++) {
                ch_group4<true>(A, xs, ys, qA, P, g1v);
                ch_group4<true>(B, xs, ys, qB, P, g1v);
                qA += 4; qB += 4;
            }
        } else {
            // -------- generic per-chain scalar path (block tail only) ----
#pragma unroll 1
            for (int cidx = 0; cidx < 2; cidx++) {
                int start = cidx ? sB : sA;
                if (start >= N) continue;
                int nstart = start - WARM; if (nstart < 0) nstart = 0;
                int nend   = start + LCH;  if (nend > N)   nend = N;
                Ch C;
                ch_seed(C, nstart, nstart - regionStart, scaleF, Hm2, sc, h0, xs);
                int q = (cidx ? (TPB + t) : t) * LCH;
                for (int n = nstart; n < nend; ++n) {
                    if (C.fr >= C.frLim) {
                        C.i0++; C.rw += 10;
                        ch_reload(C, Hm2);
                        C.fr -= 1.0f;
                    }
                    float xv = xs[C.j + (C.j >> 5)];
                    float v1 = fmaf(P.b2c, C.x2, fmaf(P.b1c, C.x1, P.b0 * xv));
                    C.x2 = C.x1; C.x1 = xv;
                    float hcur = fmaf(-P.a2, C.f2, fmaf(-P.a1, C.f1, v1));
                    float c0 = fmaf(C.fr, C.db0, C.cb0);
                    float c1 = fmaf(C.fr, C.db1, C.cb1);
                    float c2 = fmaf(C.fr, C.db2, C.cb2);
                    float c3 = fmaf(C.fr, C.db3, C.cb3);
                    float c4 = fmaf(C.fr, C.db4, C.cb4);
                    float v = fmaf(c0, hcur, fmaf(c1, C.f1, fmaf(c2, C.f2, fmaf(c3, C.f3, c4 * C.f4))));
                    float d1 = fmaf(C.fr, C.dd1, C.cd1);
                    float d2 = fmaf(C.fr, C.dd2, C.cd2);
                    float d3 = fmaf(C.fr, C.dd3, C.cd3);
                    float d4 = fmaf(C.fr, C.dd4, C.cd4);
                    float yv = fmaf(-d1, C.y1, v - fmaf(d2, C.y2, fmaf(d3, C.y3, d4 * C.y4)));
                    C.y4 = C.y3; C.y3 = C.y2; C.y2 = C.y1; C.y1 = yv;
                    C.f4 = C.f3; C.f3 = C.f2; C.f2 = C.f1; C.f1 = hcur;
                    C.fr += scaleF;
                    C.j++;
                    if (n >= start) { ys[q + (q >> 5)] = fmaf(g1v, hcur, yv); q++; }
                }
            }
        }
    }
    __syncthreads();

    // ---- coalesced epilogue: shared ys -> global out ----
    {
        const int outLim = out_size < N ? out_size : N;
        for (int idx = threadIdx.x; idx < PAYN; idx += TPB) {
            int g = blockSampleBase + idx;
            if (g < outLim) out[g] = ys[idx + (idx >> 5)];
        }
    }
}

// ---------------- launch ----------------
extern "C" void kernel_launch(void* const* d_in, const int* in_sizes, int n_in,
                              void* d_out, int out_size)
{
    const float* x      = (const float*)d_in[0];
    const float* g1     = (const float*)d_in[1];
    const float* g2     = (const float*)d_in[2];
    const float* depth  = (const float*)d_in[3];
    const float* bias   = (const float*)d_in[4];
    const float* lfo_o  = (const float*)d_in[5];
    const float* lfo_p  = (const float*)d_in[6];
    const float* lfo_r  = (const float*)d_in[7];
    const float* W_in   = (const float*)d_in[8];
    const float* b_in   = (const float*)d_in[9];
    const float* W_h    = (const float*)d_in[10];
    const float* b_h    = (const float*)d_in[11];
    const float* W_out  = (const float*)d_in[12];
    const float* b_out  = (const float*)d_in[13];
    const float* bq_dc  = (const float*)d_in[14];
    const float* bq_ff  = (const float*)d_in[15];
    const float* bq_fb  = (const float*)d_in[16];
    float* out = (float*)d_out;

    int N = in_sizes[0];
    int H = N / 551 + 1;

    int C = (N + LCH - 1) / LCH;
    int blocks = (C + CHB - 1) / CHB;
    phaser_all<<<blocks, TPB>>>(x, g1, g2, depth, bias, lfo_o, lfo_p, lfo_r,
                                W_in, b_in, W_h, b_h, W_out, b_out,
                                bq_dc, bq_ff, bq_fb,
                                out, N, H, out_size);
}

// round 15
// speedup vs baseline: 1.4754x; 1.4754x over previous
#include <cuda_runtime.h>
#include <math.h>

// ---------------- tuning ----------------
#define LCH  32     // samples per chunk (one chunk per thread)
#define WARM 32     // warmup (measured ~1.4e-4 total rel_err incl. midpoint)
#define TPB  32     // one warp per block -> 1024 blocks
#define NCH  6      // max hop rows per block region (<=4 actual)
#define LEAD 4      // region lead-in so per-thread j starts 4-aligned

// shared padding: +4 floats every 32 -> stride 36, vec4-aligned groups,
// phase-conflict-free for both scalar(lane-stride-32) and .128 accesses
#define PAD(j) ((j) + (((j) >> 5) << 2))

__global__ void __launch_bounds__(TPB)
phaser_all(const float* __restrict__ x,
           const float* __restrict__ g1, const float* __restrict__ g2,
           const float* __restrict__ depth, const float* __restrict__ bias,
           const float* __restrict__ lfo_omega, const float* __restrict__ lfo_phi,
           const float* __restrict__ lfo_r_logit,
           const float* __restrict__ W_in, const float* __restrict__ b_in,
           const float* __restrict__ W_h, const float* __restrict__ b_h,
           const float* __restrict__ W_out, const float* __restrict__ b_out,
           const float* __restrict__ bq_dc, const float* __restrict__ bq_ff,
           const float* __restrict__ bq_fb,
           float* __restrict__ out, int N, int H, int out_size)
{
    constexpr int REGN = TPB * LCH + WARM + LEAD;  // 1060 (multiple of 4)
    constexpr int PAYN = TPB * LCH;                // 1024
    __shared__ __align__(16) float xs[REGN + ((REGN >> 5) << 2) + 8];
    __shared__ __align__(16) float ys[PAYN + ((PAYN >> 5) << 2) + 8];
    __shared__ float sc[NCH * 10];                 // per hop: cb[0..4], cd[0..4]
    __shared__ float mh[2][NCH * 16];              // MLP hidden ping-pong

    const int blockFirst      = blockIdx.x * TPB;  // first chunk id
    const int blockSampleBase = blockFirst * LCH;
    const int regionStart     = blockSampleBase - WARM - LEAD;   // 16B-aligned
    const float scaleF = (float)((double)(H - 1) / (double)(N - 1));
    const int Hm2 = (H - 2) > 0 ? (H - 2) : 0;

    // ---- stage x into shared ----
    if (regionStart >= 0 && regionStart + REGN <= N) {
        // interior fast path: vec4, unconditional
        const float4* xv4 = (const float4*)(x + regionStart);
#pragma unroll
        for (int v = threadIdx.x; v < REGN / 4; v += TPB) {
            float4 t = xv4[v];
            *(float4*)(xs + PAD(4 * v)) = t;
        }
    } else {
        // boundary blocks: scalar with zero fill
        for (int j = threadIdx.x; j < REGN; j += TPB) {
            int g = regionStart + j;
            xs[PAD(j)] = (g >= 0 && g < N) ? x[g] : 0.f;
        }
    }

    // ---- hop-row range this block needs ----
    int nmin = regionStart + LEAD; if (nmin < 0) nmin = 0;
    int nmaxx = blockSampleBase + PAYN; if (nmaxx > N) nmaxx = N;
    int i0min = (int)floorf((float)nmin * scaleF);
    if (i0min < 0) i0min = 0; if (i0min > Hm2) i0min = Hm2;
    int i0max = (int)floorf((float)(nmaxx - 1) * scaleF);
    if (i0max < 0) i0max = 0; if (i0max > Hm2) i0max = Hm2;
    const int h0 = i0min;
    int nh = i0max + 2 - h0; if (nh > NCH) nh = NCH;
    const int nwork = nh * 16;

    // ---- parallel MLP: layer 0 ----
    {
        float r    = 1.f / (1.f + expf(-lfo_r_logit[0]));
        float logr = logf(r);
        float om = lfo_omega[0], phi = lfo_phi[0];
        for (int w = threadIdx.x; w < nwork; w += TPB) {
            int hop = w >> 4, u = w & 15;
            float tf  = (float)(h0 + hop);
            float amp = expf(tf * logr);            // r^t
            float ph  = om * tf + phi;
            float l0 = amp * cosf(ph), l1 = amp * sinf(ph);
            mh[0][w] = tanhf(l0 * W_in[u] + l1 * W_in[16 + u] + b_in[u]);
        }
    }
    __syncthreads();
#pragma unroll
    for (int lay = 0; lay < 2; lay++) {
        for (int w = threadIdx.x; w < nwork; w += TPB) {
            int hop = w >> 4, u = w & 15;
            const float* hv = &mh[lay & 1][hop << 4];
            float s = b_h[lay * 16 + u];
#pragma unroll
            for (int i = 0; i < 16; i++)
                s = fmaf(hv[i], W_h[lay * 256 + i * 16 + u], s);
            mh[(lay & 1) ^ 1][w] = tanhf(s);
        }
        __syncthreads();
    }
    // ---- output layer + allpass coefficient rows (one thread per hop) ----
    if (threadIdx.x < nh) {
        int t = h0 + threadIdx.x;
        const float* hv = &mh[0][threadIdx.x << 4];
        float s = b_out[0];
#pragma unroll
        for (int i = 0; i < 16; i++) s = fmaf(hv[i], W_out[i], s);
        float ws = tanhf(s);
        float dd = bias[0] + depth[0] * 0.5f * (1.f + ws);
        float td = tanf(dd);
        float p  = tanhf((1.f - td) / (1.f + td));
        float p2 = p * p, p3 = p2 * p, p4 = p2 * p2;
        float bap[5] = { p4, -4.f * p3, 6.f * p2, -4.f * p, 1.f };
        float aap[5] = { 1.f, -4.f * p, 6.f * p2, -4.f * p3, p4 };
        float ag2 = fabsf(g2[0]);
        float den0 = aap[0] - ag2 * bap[0];
        float* row = sc + threadIdx.x * 10;
#pragma unroll
        for (int k = 0; k < 5; k++) {
            float dk = aap[k] - ag2 * bap[k];
            row[k]     = bap[k] / den0;
            row[5 + k] = dk / den0;
        }
        if (N + t < out_size) out[N + t] = p;       // second output: p (H,)
        if (t == H - 1 && blockIdx.x == gridDim.x - 1)
            for (int q2 = N + H; q2 < out_size; q2++) out[q2] = p;
    }
    __syncthreads();

    // ---- per-thread chunk ----
    const int c     = blockFirst + threadIdx.x;
    const int start = c * LCH;
    if (start < N) {
        int nstart = start - WARM; if (nstart < 0) nstart = 0;
        int nend   = start + LCH;  if (nend > N)   nend = N;

        const float b0  = bq_dc[0], b1c = bq_ff[0], b2c = bq_ff[1];
        const float a1  = 2.f * tanhf(bq_fb[0]);
        const float aa1 = fabsf(a1);
        const float a2  = ((2.f - aa1) * tanhf(bq_fb[1]) + aa1) * 0.5f;
        const float g1v = g1[0];
        const float sF1 = scaleF, sF4 = 4.f * scaleF;
        const float sFm = 1.5f * scaleF;           // group-midpoint offset

        int j = nstart - regionStart;              // 4-aligned in fast path
        float x1 = xs[PAD(j - 1)];
        float x2 = xs[PAD(j - 2)];
        float f1 = 0.f, f2 = 0.f, f3 = 0.f, f4 = 0.f;
        float y1 = 0.f, y2v = 0.f, y3 = 0.f, y4 = 0.f;

        float cb00,cb01,cb02,cb03,cb04, cbd0,cbd1,cbd2,cbd3,cbd4;
        float cd01,cd02,cd03,cd04, cdd1,cdd2,cdd3,cdd4;
        int i0;
        const float* rw;
        float fr, frLim;

#define RELOAD_ROWS()                                                          \
    {                                                                          \
        cb00 = rw[0];  cb01 = rw[1];  cb02 = rw[2];  cb03 = rw[3];  cb04 = rw[4]; \
        cd01 = rw[6];  cd02 = rw[7];  cd03 = rw[8];  cd04 = rw[9];             \
        cbd0 = rw[10] - cb00; cbd1 = rw[11] - cb01; cbd2 = rw[12] - cb02;      \
        cbd3 = rw[13] - cb03; cbd4 = rw[14] - cb04;                            \
        cdd1 = rw[16] - cd01; cdd2 = rw[17] - cd02;                            \
        cdd3 = rw[18] - cd03; cdd4 = rw[19] - cd04;                            \
        frLim = (i0 < Hm2) ? 1.0f : 1e30f;                                     \
    }

        {
            float pos0 = (float)nstart * scaleF;   // exact reference seed
            i0 = (int)floorf(pos0);
            i0 = i0 < 0 ? 0 : (i0 > Hm2 ? Hm2 : i0);
            rw = sc + (i0 - h0) * 10;
            RELOAD_ROWS();
            fr = pos0 - (float)i0;
        }

        // one step with group-constant coefficients; XV from pre-loaded vec4
#define STEP(XV, XM1, XM2, H1, H2, H3, H4, HN, Y1, Y2, Y3, Y4, YN, YOUT)       \
    {                                                                          \
        float v1 = fmaf(b2c, XM2, fmaf(b1c, XM1, b0 * XV));                    \
        HN = fmaf(-a2, H2, fmaf(-a1, H1, v1));                                 \
        float v = fmaf(gc0, HN, fmaf(gc1, H1, fmaf(gc2, H2, fmaf(gc3, H3, gc4 * H4)))); \
        YN = fmaf(-gd1, Y1, v - fmaf(gd2, Y2, fmaf(gd3, Y3, gd4 * Y4)));       \
        YOUT = fmaf(g1v, HN, YN);                                              \
    }

        // group of 4: crossing check + midpoint coeffs + vec4 LDS/STS
#define GROUP4(DOST, Q)                                                        \
    {                                                                          \
        if (fr >= frLim) {                                                     \
            i0++; rw += 10;                                                    \
            RELOAD_ROWS();                                                     \
            fr -= 1.0f;                                                        \
        }                                                                      \
        float frm = fr + sFm;                                                  \
        float gc0 = fmaf(frm, cbd0, cb00);                                     \
        float gc1 = fmaf(frm, cbd1, cb01);                                     \
        float gc2 = fmaf(frm, cbd2, cb02);                                     \
        float gc3 = fmaf(frm, cbd3, cb03);                                     \
        float gc4 = fmaf(frm, cbd4, cb04);                                     \
        float gd1 = fmaf(frm, cdd1, cd01);                                     \
        float gd2 = fmaf(frm, cdd2, cd02);                                     \
        float gd3 = fmaf(frm, cdd3, cd03);                                     \
        float gd4 = fmaf(frm, cdd4, cd04);                                     \
        float4 xq = *(const float4*)(xs + PAD(j));                             \
        float ha, hb, hc, hd, ya, yb, yc, yd, oa, ob, oc, od;                  \
        STEP(xq.x, x1,   x2, f1, f2, f3, f4, ha, y1, y2v, y3, y4, ya, oa)      \
        STEP(xq.y, xq.x, x1, ha, f1, f2, f3, hb, ya, y1, y2v, y3, yb, ob)      \
        STEP(xq.z, xq.y, xq.x, hb, ha, f1, f2, hc, yb, ya, y1, y2v, yc, oc)    \
        STEP(xq.w, xq.z, xq.y, hc, hb, ha, f1, hd, yc, yb, ya, y1, yd, od)     \
        if (DOST) {                                                            \
            float4 yq; yq.x = oa; yq.y = ob; yq.z = oc; yq.w = od;             \
            *(float4*)(ys + PAD(Q)) = yq;                                      \
        }                                                                      \
        x2 = xq.z; x1 = xq.w;                                                  \
        f4 = ha; f3 = hb; f2 = hc; f1 = hd;                                    \
        y4 = ya; y3 = yb; y2v = yc; y1 = yd;                                   \
        fr += sF4;                                                             \
        j += 4;                                                                \
    }

        int n = nstart;
        if (((nend - nstart) & 3) == 0 && (j & 3) == 0) {
            // fast path: 4-aligned j, lengths multiple of 4
            for (; n < start; n += 4) GROUP4(0, 0)
            int q = threadIdx.x * LCH;
            for (; n < nend; n += 4) { GROUP4(1, q) q += 4; }
        } else {
            // generic fallback (boundary chunks): exact per-sample interp
            int q = threadIdx.x * LCH;
            for (; n < nend; ++n) {
                if (fr >= frLim) {
                    i0++; rw += 10;
                    RELOAD_ROWS();
                    fr -= 1.0f;
                }
                float xv = xs[PAD(j)];
                float v1 = fmaf(b2c, x2, fmaf(b1c, x1, b0 * xv));
                x2 = x1; x1 = xv;
                float hcur = fmaf(-a2, f2, fmaf(-a1, f1, v1));
                float c0 = fmaf(fr, cbd0, cb00);
                float c1 = fmaf(fr, cbd1, cb01);
                float c2 = fmaf(fr, cbd2, cb02);
                float c3 = fmaf(fr, cbd3, cb03);
                float c4 = fmaf(fr, cbd4, cb04);
                float v = fmaf(c0, hcur, fmaf(c1, f1, fmaf(c2, f2, fmaf(c3, f3, c4 * f4))));
                float d1 = fmaf(fr, cdd1, cd01);
                float d2 = fmaf(fr, cdd2, cd02);
                float d3 = fmaf(fr, cdd3, cd03);
                float d4 = fmaf(fr, cdd4, cd04);
                float yv = fmaf(-d1, y1, v - fmaf(d2, y2v, fmaf(d3, y3, d4 * y4)));
                y4 = y3; y3 = y2v; y2v = y1; y1 = yv;
                f4 = f3; f3 = f2; f2 = f1; f1 = hcur;
                fr += sF1;
                j++;
                if (n >= start) { ys[PAD(q)] = fmaf(g1v, hcur, yv); q++; }
            }
        }
#undef GROUP4
#undef STEP
#undef RELOAD_ROWS
    }
    __syncthreads();

    // ---- coalesced epilogue: shared ys -> global out (vec4) ----
    {
        const int outLim = out_size < N ? out_size : N;
#pragma unroll
        for (int v = threadIdx.x; v < PAYN / 4; v += TPB) {
            int g = blockSampleBase + 4 * v;
            if (g + 4 <= outLim) {
                *(float4*)(out + g) = *(const float4*)(ys + PAD(4 * v));
            } else {
                for (int k = 0; k < 4; k++)
                    if (g + k < outLim) out[g + k] = ys[PAD(4 * v + k)];
            }
        }
    }
}

// ---------------- launch ----------------
extern "C" void kernel_launch(void* const* d_in, const int* in_sizes, int n_in,
                              void* d_out, int out_size)
{
    const float* x      = (const float*)d_in[0];
    const float* g1     = (const float*)d_in[1];
    const float* g2     = (const float*)d_in[2];
    const float* depth  = (const float*)d_in[3];
    const float* bias   = (const float*)d_in[4];
    const float* lfo_o  = (const float*)d_in[5];
    const float* lfo_p  = (const float*)d_in[6];
    const float* lfo_r  = (const float*)d_in[7];
    const float* W_in   = (const float*)d_in[8];
    const float* b_in   = (const float*)d_in[9];
    const float* W_h    = (const float*)d_in[10];
    const float* b_h    = (const float*)d_in[11];
    const float* W_out  = (const float*)d_in[12];
    const float* b_out  = (const float*)d_in[13];
    const float* bq_dc  = (const float*)d_in[14];
    const float* bq_ff  = (const float*)d_in[15];
    const float* bq_fb  = (const float*)d_in[16];
    float* out = (float*)d_out;

    int N = in_sizes[0];
    int H = N / 551 + 1;

    int C = (N + LCH - 1) / LCH;
    int blocks = (C + TPB - 1) / TPB;
    phaser_all<<<blocks, TPB>>>(x, g1, g2, depth, bias, lfo_o, lfo_p, lfo_r,
                                W_in, b_in, W_h, b_h, W_out, b_out,
                                bq_dc, bq_ff, bq_fb,
                                out, N, H, out_size);
}

// round 16
// speedup vs baseline: 1.5050x; 1.0201x over previous
#include <cuda_runtime.h>
#include <math.h>

// ---------------- tuning ----------------
#define LCH  32     // samples per chunk (one chunk per thread)
#define WARM 32     // warmup (measured ~1.4e-4 total rel_err incl. midpoint)
#define TPB  32     // one warp per block -> 1024 blocks
#define NCH  6      // max hop rows per block region (<=4 actual)
#define LEAD 4      // region lead-in so per-thread j starts 4-aligned
#define MAXH 2048
#define HPB  8      // hops per coef block -> nwork = 128 = coef TPB

// per-hop coefficient rows: [cb0..cb4, cd0..cd4] * H
__device__ float g_sc[MAXH * 10];

// shared padding: +4 floats every 32 -> stride 36, vec4-aligned groups
#define PAD(j) ((j) + (((j) >> 5) << 2))

__device__ __forceinline__ float ftanh(float v) {
    float e = __expf(2.f * v);                 // args O(1-3): safe + accurate
    return __fdividef(e - 1.f, e + 1.f);
}

// ---------------- kernel A: all hop coefficients -> g_sc ----------------
__global__ void __launch_bounds__(128)
coef_kernel(const float* __restrict__ g2,
            const float* __restrict__ depth, const float* __restrict__ bias,
            const float* __restrict__ lfo_omega, const float* __restrict__ lfo_phi,
            const float* __restrict__ lfo_r_logit,
            const float* __restrict__ W_in, const float* __restrict__ b_in,
            const float* __restrict__ W_h, const float* __restrict__ b_h,
            const float* __restrict__ W_out, const float* __restrict__ b_out,
            float* __restrict__ out, int N, int H, int out_size)
{
    __shared__ float mh[2][HPB * 16];
    const int h0 = blockIdx.x * HPB;
    const int tid = threadIdx.x;
    int nh = H - h0; if (nh > HPB) nh = HPB; if (nh <= 0) return;
    const int nwork = nh * 16;

    // layer 0 (one (hop,unit) item per thread)
    if (tid < nwork) {
        int hop = tid >> 4, u = tid & 15;
        float r   = 1.f / (1.f + expf(-lfo_r_logit[0]));
        float tf  = (float)(h0 + hop);
        float amp = expf(tf * logf(r));        // precise: log near 1
        float ph  = lfo_omega[0] * tf + lfo_phi[0];
        float l0 = amp * cosf(ph), l1 = amp * sinf(ph);
        mh[0][tid] = ftanh(l0 * W_in[u] + l1 * W_in[16 + u] + b_in[u]);
    }
    __syncthreads();
#pragma unroll
    for (int lay = 0; lay < 2; lay++) {
        if (tid < nwork) {
            int hop = tid >> 4, u = tid & 15;
            const float* hv = &mh[lay & 1][hop << 4];
            float s = b_h[lay * 16 + u];
#pragma unroll
            for (int i = 0; i < 16; i++)
                s = fmaf(hv[i], W_h[lay * 256 + i * 16 + u], s);
            mh[(lay & 1) ^ 1][tid] = ftanh(s);
        }
        __syncthreads();
    }
    // output layer + allpass rows (one thread per hop)
    if (tid < nh) {
        int t = h0 + tid;
        const float* hv = &mh[0][tid << 4];
        float s = b_out[0];
#pragma unroll
        for (int i = 0; i < 16; i++) s = fmaf(hv[i], W_out[i], s);
        float ws = ftanh(s);
        float dd = bias[0] + depth[0] * 0.5f * (1.f + ws);
        float td = __tanf(dd);
        float p  = ftanh(__fdividef(1.f - td, 1.f + td));
        float p2 = p * p, p3 = p2 * p, p4 = p2 * p2;
        float bap[5] = { p4, -4.f * p3, 6.f * p2, -4.f * p, 1.f };
        float aap[5] = { 1.f, -4.f * p, 6.f * p2, -4.f * p3, p4 };
        float ag2 = fabsf(g2[0]);
        float den0 = aap[0] - ag2 * bap[0];
        float* row = g_sc + t * 10;
#pragma unroll
        for (int k = 0; k < 5; k++) {
            float dk = aap[k] - ag2 * bap[k];
            row[k]     = __fdividef(bap[k], den0);
            row[5 + k] = __fdividef(dk, den0);
        }
        if (N + t < out_size) out[N + t] = p;   // second output: p (H,)
        if (t == H - 1)
            for (int q2 = N + H; q2 < out_size; q2++) out[q2] = p;
    }
}

// ---------------- kernel B: fused biquad + TV-FIR + TV-LPC ----------------
__global__ void __launch_bounds__(TPB)
phaser_kernel(const float* __restrict__ x,
              const float* __restrict__ g1,
              const float* __restrict__ bq_dc, const float* __restrict__ bq_ff,
              const float* __restrict__ bq_fb,
              float* __restrict__ out, int N, int H, int out_size)
{
    constexpr int REGN = TPB * LCH + WARM + LEAD;  // 1060
    constexpr int PAYN = TPB * LCH;                // 1024
    __shared__ __align__(16) float xs[REGN + ((REGN >> 5) << 2) + 8];
    __shared__ __align__(16) float ys[PAYN + ((PAYN >> 5) << 2) + 8];
    __shared__ float sc[NCH * 10];

    const int blockFirst      = blockIdx.x * TPB;
    const int blockSampleBase = blockFirst * LCH;
    const int regionStart     = blockSampleBase - WARM - LEAD;   // 16B-aligned
    const float scaleF = (float)((double)(H - 1) / (double)(N - 1));
    const int Hm2 = (H - 2) > 0 ? (H - 2) : 0;

    // ---- hop-row range this block needs ----
    int nmin = regionStart + LEAD; if (nmin < 0) nmin = 0;
    int nmaxx = blockSampleBase + PAYN; if (nmaxx > N) nmaxx = N;
    int i0min = (int)floorf((float)nmin * scaleF);
    if (i0min < 0) i0min = 0; if (i0min > Hm2) i0min = Hm2;
    int i0max = (int)floorf((float)(nmaxx - 1) * scaleF);
    if (i0max < 0) i0max = 0; if (i0max > Hm2) i0max = Hm2;
    const int h0 = i0min;
    int nh = i0max + 2 - h0; if (nh > NCH) nh = NCH;

    // ---- stage coeff rows (overlaps with x staging below) ----
    for (int i = threadIdx.x; i < nh * 10; i += TPB)
        sc[i] = g_sc[h0 * 10 + i];

    // ---- stage x into shared ----
    if (regionStart >= 0 && regionStart + REGN <= N) {
        const float4* xv4 = (const float4*)(x + regionStart);
#pragma unroll
        for (int v = threadIdx.x; v < REGN / 4; v += TPB) {
            float4 t = xv4[v];
            *(float4*)(xs + PAD(4 * v)) = t;
        }
    } else {
        for (int j = threadIdx.x; j < REGN; j += TPB) {
            int g = regionStart + j;
            xs[PAD(j)] = (g >= 0 && g < N) ? x[g] : 0.f;
        }
    }
    __syncthreads();

    // ---- per-thread chunk ----
    const int c     = blockFirst + threadIdx.x;
    const int start = c * LCH;
    if (start < N) {
        int nstart = start - WARM; if (nstart < 0) nstart = 0;
        int nend   = start + LCH;  if (nend > N)   nend = N;

        const float b0  = bq_dc[0], b1c = bq_ff[0], b2c = bq_ff[1];
        const float a1  = 2.f * tanhf(bq_fb[0]);
        const float aa1 = fabsf(a1);
        const float a2  = ((2.f - aa1) * tanhf(bq_fb[1]) + aa1) * 0.5f;
        const float g1v = g1[0];
        const float sF1 = scaleF, sF4 = 4.f * scaleF;
        const float sFm = 1.5f * scaleF;

        int j = nstart - regionStart;              // 4-aligned in fast path
        float x1 = xs[PAD(j - 1)];
        float x2 = xs[PAD(j - 2)];
        float f1 = 0.f, f2 = 0.f, f3 = 0.f, f4 = 0.f;
        float y1 = 0.f, y2v = 0.f, y3 = 0.f, y4 = 0.f;

        float cb00,cb01,cb02,cb03,cb04, cbd0,cbd1,cbd2,cbd3,cbd4;
        float cd01,cd02,cd03,cd04, cdd1,cdd2,cdd3,cdd4;
        int i0;
        const float* rw;
        float fr, frLim;

#define RELOAD_ROWS()                                                          \
    {                                                                          \
        cb00 = rw[0];  cb01 = rw[1];  cb02 = rw[2];  cb03 = rw[3];  cb04 = rw[4]; \
        cd01 = rw[6];  cd02 = rw[7];  cd03 = rw[8];  cd04 = rw[9];             \
        cbd0 = rw[10] - cb00; cbd1 = rw[11] - cb01; cbd2 = rw[12] - cb02;      \
        cbd3 = rw[13] - cb03; cbd4 = rw[14] - cb04;                            \
        cdd1 = rw[16] - cd01; cdd2 = rw[17] - cd02;                            \
        cdd3 = rw[18] - cd03; cdd4 = rw[19] - cd04;                            \
        frLim = (i0 < Hm2) ? 1.0f : 1e30f;                                     \
    }

        {
            float pos0 = (float)nstart * scaleF;   // exact reference seed
            i0 = (int)floorf(pos0);
            i0 = i0 < 0 ? 0 : (i0 > Hm2 ? Hm2 : i0);
            rw = sc + (i0 - h0) * 10;
            RELOAD_ROWS();
            fr = pos0 - (float)i0;
        }

#define STEP(XV, XM1, XM2, H1, H2, H3, H4, HN, Y1, Y2, Y3, Y4, YN, YOUT)       \
    {                                                                          \
        float v1 = fmaf(b2c, XM2, fmaf(b1c, XM1, b0 * XV));                    \
        HN = fmaf(-a2, H2, fmaf(-a1, H1, v1));                                 \
        float v = fmaf(gc0, HN, fmaf(gc1, H1, fmaf(gc2, H2, fmaf(gc3, H3, gc4 * H4)))); \
        YN = fmaf(-gd1, Y1, v - fmaf(gd2, Y2, fmaf(gd3, Y3, gd4 * Y4)));       \
        YOUT = fmaf(g1v, HN, YN);                                              \
    }

#define GROUP4(DOST, Q)                                                        \
    {                                                                          \
        if (fr >= frLim) {                                                     \
            i0++; rw += 10;                                                    \
            RELOAD_ROWS();                                                     \
            fr -= 1.0f;                                                        \
        }                                                                      \
        float frm = fr + sFm;                                                  \
        float gc0 = fmaf(frm, cbd0, cb00);                                     \
        float gc1 = fmaf(frm, cbd1, cb01);                                     \
        float gc2 = fmaf(frm, cbd2, cb02);                                     \
        float gc3 = fmaf(frm, cbd3, cb03);                                     \
        float gc4 = fmaf(frm, cbd4, cb04);                                     \
        float gd1 = fmaf(frm, cdd1, cd01);                                     \
        float gd2 = fmaf(frm, cdd2, cd02);                                     \
        float gd3 = fmaf(frm, cdd3, cd03);                                     \
        float gd4 = fmaf(frm, cdd4, cd04);                                     \
        float4 xq = *(const float4*)(xs + PAD(j));                             \
        float ha, hb, hc, hd, ya, yb, yc, yd, oa, ob, oc, od;                  \
        STEP(xq.x, x1,   x2, f1, f2, f3, f4, ha, y1, y2v, y3, y4, ya, oa)      \
        STEP(xq.y, xq.x, x1, ha, f1, f2, f3, hb, ya, y1, y2v, y3, yb, ob)      \
        STEP(xq.z, xq.y, xq.x, hb, ha, f1, f2, hc, yb, ya, y1, y2v, yc, oc)    \
        STEP(xq.w, xq.z, xq.y, hc, hb, ha, f1, hd, yc, yb, ya, y1, yd, od)     \
        if (DOST) {                                                            \
            float4 yq; yq.x = oa; yq.y = ob; yq.z = oc; yq.w = od;             \
            *(float4*)(ys + PAD(Q)) = yq;                                      \
        }                                                                      \
        x2 = xq.z; x1 = xq.w;                                                  \
        f4 = ha; f3 = hb; f2 = hc; f1 = hd;                                    \
        y4 = ya; y3 = yb; y2v = yc; y1 = yd;                                   \
        fr += sF4;                                                             \
        j += 4;                                                                \
    }

        int n = nstart;
        if (((nend - nstart) & 3) == 0 && (j & 3) == 0) {
            for (; n < start; n += 4) GROUP4(0, 0)
            int q = threadIdx.x * LCH;
            for (; n < nend; n += 4) { GROUP4(1, q) q += 4; }
        } else {
            int q = threadIdx.x * LCH;
            for (; n < nend; ++n) {
                if (fr >= frLim) {
                    i0++; rw += 10;
                    RELOAD_ROWS();
                    fr -= 1.0f;
                }
                float xv = xs[PAD(j)];
                float v1 = fmaf(b2c, x2, fmaf(b1c, x1, b0 * xv));
                x2 = x1; x1 = xv;
                float hcur = fmaf(-a2, f2, fmaf(-a1, f1, v1));
                float c0 = fmaf(fr, cbd0, cb00);
                float c1 = fmaf(fr, cbd1, cb01);
                float c2 = fmaf(fr, cbd2, cb02);
                float c3 = fmaf(fr, cbd3, cb03);
                float c4 = fmaf(fr, cbd4, cb04);
                float v = fmaf(c0, hcur, fmaf(c1, f1, fmaf(c2, f2, fmaf(c3, f3, c4 * f4))));
                float d1 = fmaf(fr, cdd1, cd01);
                float d2 = fmaf(fr, cdd2, cd02);
                float d3 = fmaf(fr, cdd3, cd03);
                float d4 = fmaf(fr, cdd4, cd04);
                float yv = fmaf(-d1, y1, v - fmaf(d2, y2v, fmaf(d3, y3, d4 * y4)));
                y4 = y3; y3 = y2v; y2v = y1; y1 = yv;
                f4 = f3; f3 = f2; f2 = f1; f1 = hcur;
                fr += sF1;
                j++;
                if (n >= start) { ys[PAD(q)] = fmaf(g1v, hcur, yv); q++; }
            }
        }
#undef GROUP4
#undef STEP
#undef RELOAD_ROWS
    }
    __syncthreads();

    // ---- coalesced epilogue: shared ys -> global out (vec4) ----
    {
        const int outLim = out_size < N ? out_size : N;
#pragma unroll
        for (int v = threadIdx.x; v < PAYN / 4; v += TPB) {
            int g = blockSampleBase + 4 * v;
            if (g + 4 <= outLim) {
                *(float4*)(out + g) = *(const float4*)(ys + PAD(4 * v));
            } else {
                for (int k = 0; k < 4; k++)
                    if (g + k < outLim) out[g + k] = ys[PAD(4 * v + k)];
            }
        }
    }
}

// ---------------- launch ----------------
extern "C" void kernel_launch(void* const* d_in, const int* in_sizes, int n_in,
                              void* d_out, int out_size)
{
    const float* x      = (const float*)d_in[0];
    const float* g1     = (const float*)d_in[1];
    const float* g2     = (const float*)d_in[2];
    const float* depth  = (const float*)d_in[3];
    const float* bias   = (const float*)d_in[4];
    const float* lfo_o  = (const float*)d_in[5];
    const float* lfo_p  = (const float*)d_in[6];
    const float* lfo_r  = (const float*)d_in[7];
    const float* W_in   = (const float*)d_in[8];
    const float* b_in   = (const float*)d_in[9];
    const float* W_h    = (const float*)d_in[10];
    const float* b_h    = (const float*)d_in[11];
    const float* W_out  = (const float*)d_in[12];
    const float* b_out  = (const float*)d_in[13];
    const float* bq_dc  = (const float*)d_in[14];
    const float* bq_ff  = (const float*)d_in[15];
    const float* bq_fb  = (const float*)d_in[16];
    float* out = (float*)d_out;

    int N = in_sizes[0];
    int H = N / 551 + 1;

    int cblocks = (H + HPB - 1) / HPB;
    coef_kernel<<<cblocks, 128>>>(g2, depth, bias, lfo_o, lfo_p, lfo_r,
                                  W_in, b_in, W_h, b_h, W_out, b_out,
                                  out, N, H, out_size);

    int C = (N + LCH - 1) / LCH;
    int blocks = (C + TPB - 1) / TPB;
    phaser_kernel<<<blocks, TPB>>>(x, g1, bq_dc, bq_ff, bq_fb,
                                   out, N, H, out_size);
}